// round 2
// baseline (speedup 1.0000x reference)
#include <cuda_runtime.h>
#include <math.h>

#define NN 50000
#define NE 800000
#define NG 64

// ---------------- static scratch (no allocations allowed) ----------------
__device__ __align__(16) float  g_h1[NN * 128];    // x@W1
__device__ __align__(16) float  g_out1[NN * 128];  // elu(conv1 out + b1)
__device__ __align__(16) float  g_h2[NN * 32];     // out1@W2
__device__ float4 g_alpha1[NE];                    // per real edge alpha, 4 heads
__device__ float4 g_t1[NE];                        // per real edge dot(ea, ae1[:,h])
__device__ float  g_alpha2[NE];
__device__ float  g_t2[NE];
__device__ float  g_als1[NN * 4];
__device__ float  g_ald1[NN * 4];
__device__ float  g_als2[NN];
__device__ float  g_ald2[NN];
__device__ int    g_deg[NN];
__device__ int    g_off[NN + 1];
__device__ int    g_cursor[NN];
__device__ int    g_csr[NE];
__device__ float  g_ae1[32];   // [8][4] folded We1 * att_e1
__device__ float  g_ae2[8];    // folded We2 * att_e2
__device__ float  g_gsum[NG * 32];
__device__ float  g_gcnt[NG];

__device__ __forceinline__ float leaky(float a) { return a > 0.f ? a : 0.2f * a; }
__device__ __forceinline__ float elu(float a)   { return a > 0.f ? a : expm1f(a); }

// ---------------- zero accumulators ----------------
__global__ void k_zero() {
    int i = blockIdx.x * blockDim.x + threadIdx.x;
    if (i < NN) { g_deg[i] = 0; g_cursor[i] = 0; }
    if (i < NG * 32) g_gsum[i] = 0.f;
    if (i < NG) g_gcnt[i] = 0.f;
}

// ---------------- degree count (int atomics only) ----------------
__global__ void k_degree(const int* __restrict__ ei) {
    int e = blockIdx.x * blockDim.x + threadIdx.x;
    if (e >= NE) return;
    atomicAdd(&g_deg[ei[NE + e]], 1);
}

// ---------------- fast single-block scan: chunk-per-thread ----------------
__global__ void k_scan() {
    __shared__ int warpsum[32];
    const int CH = (NN + 1023) / 1024;  // 49
    int t = threadIdx.x, lane = t & 31, wid = t >> 5;
    int beg = t * CH, end = beg + CH; if (end > NN) end = NN; if (beg > NN) beg = NN;
    int s = 0;
    for (int i = beg; i < end; i++) s += g_deg[i];
    int v = s;
    #pragma unroll
    for (int o = 1; o < 32; o <<= 1) {
        int u = __shfl_up_sync(0xffffffffu, v, o);
        if (lane >= o) v += u;
    }
    if (lane == 31) warpsum[wid] = v;
    __syncthreads();
    if (wid == 0) {
        int w = warpsum[lane];
        #pragma unroll
        for (int o = 1; o < 32; o <<= 1) {
            int u = __shfl_up_sync(0xffffffffu, w, o);
            if (lane >= o) w += u;
        }
        warpsum[lane] = w;
    }
    __syncthreads();
    int run = (wid > 0 ? warpsum[wid - 1] : 0) + (v - s);  // exclusive prefix
    for (int i = beg; i < end; i++) { run += g_deg[i]; g_off[i + 1] = run; }
    if (t == 0) g_off[0] = 0;
}

// ---------------- CSR fill (real edges only, grouped by dst) ----------------
__global__ void k_fill(const int* __restrict__ ei) {
    int e = blockIdx.x * blockDim.x + threadIdx.x;
    if (e >= NE) return;
    int d = ei[NE + e];
    int pos = g_off[d] + atomicAdd(&g_cursor[d], 1);
    g_csr[pos] = e;
}

// ---------------- fold We * att_e (tiny) ----------------
__global__ void k_ae(const float* __restrict__ We1, const float* __restrict__ ae1,
                     const float* __restrict__ We2, const float* __restrict__ ae2) {
    int t = threadIdx.x;
    if (t < 32) {
        int d = t >> 2, h = t & 3;
        float s = 0.f;
        for (int c = 0; c < 32; c++) s += We1[d * 128 + h * 32 + c] * ae1[h * 32 + c];
        g_ae1[d * 4 + h] = s;
    }
    if (t < 8) {
        float s = 0.f;
        for (int c = 0; c < 32; c++) s += We2[t * 32 + c] * ae2[c];
        g_ae2[t] = s;
    }
}

// ---------------- GEMM1: h1 = x @ W1, fused per-head attention dots ----------------
__global__ void k_gemm1(const float* __restrict__ x, const float* __restrict__ W,
                        const float* __restrict__ as1, const float* __restrict__ ad1) {
    __shared__ __align__(16) float sA[64 * 16];
    __shared__ __align__(16) float sB[16 * 128];
    int t = threadIdx.x;
    int tx = t & 31, ty = t >> 5;       // warp=ty owns 8 rows, lane=tx owns 4 cols
    int n0 = blockIdx.x * 64;
    float acc[8][4];
    #pragma unroll
    for (int i = 0; i < 8; i++)
        #pragma unroll
        for (int j = 0; j < 4; j++) acc[i][j] = 0.f;

    for (int kc = 0; kc < 128; kc += 16) {
        { // A tile 64x16
            int row = t >> 2, c4 = t & 3;
            float4 v = make_float4(0.f, 0.f, 0.f, 0.f);
            if (n0 + row < NN) v = *(const float4*)&x[(n0 + row) * 128 + kc + c4 * 4];
            *(float4*)&sA[row * 16 + c4 * 4] = v;
        }
        #pragma unroll
        for (int r = 0; r < 2; r++) { // B tile 16x128
            int idx = t + r * 256;
            int row = idx >> 5, c4 = idx & 31;
            *(float4*)&sB[row * 128 + c4 * 4] = *(const float4*)&W[(kc + row) * 128 + c4 * 4];
        }
        __syncthreads();
        #pragma unroll
        for (int k = 0; k < 16; k++) {
            float4 bv = *(float4*)&sB[k * 128 + tx * 4];
            #pragma unroll
            for (int i = 0; i < 8; i++) {
                float av = sA[(ty * 8 + i) * 16 + k];
                acc[i][0] += av * bv.x; acc[i][1] += av * bv.y;
                acc[i][2] += av * bv.z; acc[i][3] += av * bv.w;
            }
        }
        __syncthreads();
    }
    float4 aS = *(const float4*)&as1[tx * 4];
    float4 aD = *(const float4*)&ad1[tx * 4];
    int head = tx >> 3;  // cols tx*4..tx*4+3 are all in head tx>>3
    #pragma unroll
    for (int i = 0; i < 8; i++) {
        int n = n0 + ty * 8 + i;
        if (n < NN)
            *(float4*)&g_h1[(size_t)n * 128 + tx * 4] =
                make_float4(acc[i][0], acc[i][1], acc[i][2], acc[i][3]);
        float ps = acc[i][0] * aS.x + acc[i][1] * aS.y + acc[i][2] * aS.z + acc[i][3] * aS.w;
        float pd = acc[i][0] * aD.x + acc[i][1] * aD.y + acc[i][2] * aD.z + acc[i][3] * aD.w;
        #pragma unroll
        for (int o = 1; o < 8; o <<= 1) {
            ps += __shfl_xor_sync(0xffffffffu, ps, o);
            pd += __shfl_xor_sync(0xffffffffu, pd, o);
        }
        if ((tx & 7) == 0 && n < NN) {
            g_als1[n * 4 + head] = ps;
            g_ald1[n * 4 + head] = pd;
        }
    }
}

// ---------------- per-edge alpha + edge term for conv1 (real edges) ----------------
__global__ void k_alpha1(const int* __restrict__ ei, const float* __restrict__ ea) {
    __shared__ float sae[32];
    if (threadIdx.x < 32) sae[threadIdx.x] = g_ae1[threadIdx.x];
    __syncthreads();
    int e = blockIdx.x * blockDim.x + threadIdx.x;
    if (e >= NE) return;
    int s = ei[e], d = ei[NE + e];
    const float* a = ea + (size_t)e * 8;
    float t0 = 0.f, t1 = 0.f, t2 = 0.f, t3 = 0.f;
    #pragma unroll
    for (int j = 0; j < 8; j++) {
        float av = a[j];
        t0 += av * sae[j * 4 + 0]; t1 += av * sae[j * 4 + 1];
        t2 += av * sae[j * 4 + 2]; t3 += av * sae[j * 4 + 3];
    }
    g_t1[e] = make_float4(t0, t1, t2, t3);
    float4 al;
    al.x = leaky(g_als1[s * 4 + 0] + g_ald1[d * 4 + 0] + t0);
    al.y = leaky(g_als1[s * 4 + 1] + g_ald1[d * 4 + 1] + t1);
    al.z = leaky(g_als1[s * 4 + 2] + g_ald1[d * 4 + 2] + t2);
    al.w = leaky(g_als1[s * 4 + 3] + g_ald1[d * 4 + 3] + t3);
    g_alpha1[e] = al;
}

// ---------------- conv1 aggregation: warp-per-node online softmax, self-loop last ----------------
__global__ void k_agg1(const int* __restrict__ ei, const float* __restrict__ b1) {
    int n = (blockIdx.x * blockDim.x + threadIdx.x) >> 5;
    int lane = threadIdx.x & 31;
    if (n >= NN) return;
    int beg = g_off[n], end = g_off[n + 1];
    float m[4], den[4], acc[4], ts[4];
    #pragma unroll
    for (int r = 0; r < 4; r++) { m[r] = -1e30f; den[r] = 0.f; acc[r] = 0.f; ts[r] = 0.f; }
    for (int j = beg; j < end; j++) {
        int eid = g_csr[j];
        int s = ei[eid];
        float4 a4 = g_alpha1[eid];
        float4 t4 = g_t1[eid];
        ts[0] += t4.x; ts[1] += t4.y; ts[2] += t4.z; ts[3] += t4.w;
        float av[4] = {a4.x, a4.y, a4.z, a4.w};
        const float* hrow = g_h1 + (size_t)s * 128 + lane;
        #pragma unroll
        for (int r = 0; r < 4; r++) {
            float aa = av[r];
            if (aa > m[r]) {
                float sc = __expf(m[r] - aa);
                den[r] *= sc; acc[r] *= sc; m[r] = aa;
            }
            float w = __expf(aa - m[r]);
            den[r] += w;
            acc[r] += w * hrow[r * 32];
        }
    }
    // self-loop: attr = mean of incoming => t_self = tsum/cnt (0 if cnt==0)
    int cnt = end - beg;
    float inv = cnt > 0 ? 1.f / (float)cnt : 0.f;
    const float* hn = g_h1 + (size_t)n * 128 + lane;
    #pragma unroll
    for (int r = 0; r < 4; r++) {
        float aa = leaky(g_als1[n * 4 + r] + g_ald1[n * 4 + r] + ts[r] * inv);
        if (aa > m[r]) {
            float sc = __expf(m[r] - aa);
            den[r] *= sc; acc[r] *= sc; m[r] = aa;
        }
        float w = __expf(aa - m[r]);
        den[r] += w;
        acc[r] += w * hn[r * 32];
        float o = acc[r] / (den[r] + 1e-16f) + b1[r * 32 + lane];
        g_out1[(size_t)n * 128 + r * 32 + lane] = elu(o);
    }
}

// ---------------- GEMM2: h2 = out1 @ W2, fused att dots ----------------
__global__ void k_gemm2(const float* __restrict__ W2,
                        const float* __restrict__ as2, const float* __restrict__ ad2) {
    __shared__ __align__(16) float sA[64 * 32];
    __shared__ __align__(16) float sB[32 * 32];
    int t = threadIdx.x;
    int tx = t & 31, ty = t >> 5;
    int n0 = blockIdx.x * 64;
    float acc[8];
    #pragma unroll
    for (int i = 0; i < 8; i++) acc[i] = 0.f;

    for (int kc = 0; kc < 128; kc += 32) {
        #pragma unroll
        for (int r = 0; r < 2; r++) {
            int idx = t + r * 256;
            int row = idx >> 3, c4 = idx & 7;
            float4 v = make_float4(0.f, 0.f, 0.f, 0.f);
            if (n0 + row < NN) v = *(const float4*)&g_out1[(size_t)(n0 + row) * 128 + kc + c4 * 4];
            *(float4*)&sA[row * 32 + c4 * 4] = v;
        }
        {
            int row = t >> 3, c4 = t & 7;
            *(float4*)&sB[row * 32 + c4 * 4] = *(const float4*)&W2[(kc + row) * 32 + c4 * 4];
        }
        __syncthreads();
        #pragma unroll
        for (int k = 0; k < 32; k++) {
            float bv = sB[k * 32 + tx];
            #pragma unroll
            for (int i = 0; i < 8; i++) acc[i] += sA[(ty * 8 + i) * 32 + k] * bv;
        }
        __syncthreads();
    }
    float aS = as2[tx], aD = ad2[tx];
    #pragma unroll
    for (int i = 0; i < 8; i++) {
        int n = n0 + ty * 8 + i;
        if (n < NN) {
            g_h2[(size_t)n * 32 + tx] = acc[i];
            float ps = acc[i] * aS, pd = acc[i] * aD;
            #pragma unroll
            for (int o = 16; o; o >>= 1) {
                ps += __shfl_xor_sync(0xffffffffu, ps, o);
                pd += __shfl_xor_sync(0xffffffffu, pd, o);
            }
            if (tx == 0) { g_als2[n] = ps; g_ald2[n] = pd; }
        }
    }
}

// ---------------- per-edge alpha + edge term for conv2 ----------------
__global__ void k_alpha2(const int* __restrict__ ei, const float* __restrict__ ea) {
    __shared__ float sae[8];
    if (threadIdx.x < 8) sae[threadIdx.x] = g_ae2[threadIdx.x];
    __syncthreads();
    int e = blockIdx.x * blockDim.x + threadIdx.x;
    if (e >= NE) return;
    int s = ei[e], d = ei[NE + e];
    const float* a = ea + (size_t)e * 8;
    float tt = 0.f;
    #pragma unroll
    for (int j = 0; j < 8; j++) tt += a[j] * sae[j];
    g_t2[e] = tt;
    g_alpha2[e] = leaky(g_als2[s] + g_ald2[d] + tt);
}

// ---------------- conv2 aggregation + fused mean-pool, self-loop last ----------------
__global__ void k_agg2(const int* __restrict__ ei, const float* __restrict__ b2,
                       const int* __restrict__ batch) {
    int n = (blockIdx.x * blockDim.x + threadIdx.x) >> 5;
    int lane = threadIdx.x & 31;
    if (n >= NN) return;
    int beg = g_off[n], end = g_off[n + 1];
    float m = -1e30f, den = 0.f, acc = 0.f, tsum = 0.f;
    for (int j = beg; j < end; j++) {
        int eid = g_csr[j];
        int s = ei[eid];
        float aa = g_alpha2[eid];
        tsum += g_t2[eid];
        if (aa > m) {
            float sc = __expf(m - aa);
            den *= sc; acc *= sc; m = aa;
        }
        float w = __expf(aa - m);
        den += w;
        acc += w * g_h2[(size_t)s * 32 + lane];
    }
    int cnt = end - beg;
    float inv = cnt > 0 ? 1.f / (float)cnt : 0.f;
    float aself = leaky(g_als2[n] + g_ald2[n] + tsum * inv);
    if (aself > m) {
        float sc = __expf(m - aself);
        den *= sc; acc *= sc; m = aself;
    }
    float w = __expf(aself - m);
    den += w;
    acc += w * g_h2[(size_t)n * 32 + lane];

    float val = elu(acc / (den + 1e-16f) + b2[lane]);
    int b = batch[n];
    atomicAdd(&g_gsum[b * 32 + lane], val);
    if (lane == 0) atomicAdd(&g_gcnt[b], 1.f);
}

// ---------------- final MLP head ----------------
__global__ void k_final(const float* __restrict__ W3, const float* __restrict__ b3,
                        const float* __restrict__ W4, const float* __restrict__ b4,
                        float* __restrict__ out) {
    int t = threadIdx.x;
    if (t >= NG) return;
    float c = fmaxf(g_gcnt[t], 1.f);
    float g[32];
    #pragma unroll
    for (int i = 0; i < 32; i++) g[i] = g_gsum[t * 32 + i] / c;
    float z[16];
    #pragma unroll
    for (int j = 0; j < 16; j++) {
        float s = b3[j];
        #pragma unroll
        for (int i = 0; i < 32; i++) s += g[i] * W3[i * 16 + j];
        z[j] = fmaxf(s, 0.f);
    }
    #pragma unroll
    for (int o = 0; o < 10; o++) {
        float s = b4[o];
        #pragma unroll
        for (int j = 0; j < 16; j++) s += z[j] * W4[j * 10 + o];
        out[t * 10 + o] = s;
    }
}

extern "C" void kernel_launch(void* const* d_in, const int* in_sizes, int n_in,
                              void* d_out, int out_size) {
    const float* x     = (const float*)d_in[0];
    const int*   ei    = (const int*)d_in[1];
    const float* ea    = (const float*)d_in[2];
    const int*   batch = (const int*)d_in[3];
    const float* W1    = (const float*)d_in[4];
    const float* as1   = (const float*)d_in[5];
    const float* ad1   = (const float*)d_in[6];
    const float* We1   = (const float*)d_in[7];
    const float* ae1   = (const float*)d_in[8];
    const float* b1    = (const float*)d_in[9];
    const float* W2    = (const float*)d_in[10];
    const float* as2   = (const float*)d_in[11];
    const float* ad2   = (const float*)d_in[12];
    const float* We2   = (const float*)d_in[13];
    const float* ae2   = (const float*)d_in[14];
    const float* b2    = (const float*)d_in[15];
    const float* W3    = (const float*)d_in[16];
    const float* b3    = (const float*)d_in[17];
    const float* W4    = (const float*)d_in[18];
    const float* b4    = (const float*)d_in[19];
    float* out = (float*)d_out;

    k_zero   <<<(NN + 255) / 256, 256>>>();
    k_degree <<<(NE + 255) / 256, 256>>>(ei);
    k_scan   <<<1, 1024>>>();
    k_fill   <<<(NE + 255) / 256, 256>>>(ei);
    k_ae     <<<1, 32>>>(We1, ae1, We2, ae2);
    k_gemm1  <<<(NN + 63) / 64, 256>>>(x, W1, as1, ad1);
    k_alpha1 <<<(NE + 255) / 256, 256>>>(ei, ea);
    k_agg1   <<<(NN + 7) / 8, 256>>>(ei, b1);
    k_gemm2  <<<(NN + 63) / 64, 256>>>(W2, as2, ad2);
    k_alpha2 <<<(NE + 255) / 256, 256>>>(ei, ea);
    k_agg2   <<<(NN + 7) / 8, 256>>>(ei, b2, batch);
    k_final  <<<1, 64>>>(W3, b3, W4, b4, out);
}

// round 3
// speedup vs baseline: 1.0721x; 1.0721x over previous
#include <cuda_runtime.h>
#include <cuda_bf16.h>
#include <mma.h>
#include <math.h>

using namespace nvcuda;

#define NN 50000
#define NE 800000
#define NG 64

// ---------------- static scratch ----------------
__device__ __align__(16) float  g_h1[NN * 128];    // x@W1
__device__ __align__(16) float  g_out1[NN * 128];  // elu(conv1 out + b1)
__device__ __align__(16) float  g_h2[NN * 32];     // out1@W2
__device__ float4 g_alpha1[NE];
__device__ float4 g_t1[NE];
__device__ float  g_alpha2[NE];
__device__ float  g_t2[NE];
__device__ float  g_als1[NN * 4];
__device__ float  g_ald1[NN * 4];
__device__ float  g_als2[NN];
__device__ float  g_ald2[NN];
__device__ int    g_deg[NN];
__device__ int    g_off[NN + 1];
__device__ int    g_cursor[NN];
__device__ int    g_csr[NE];
__device__ float  g_ae1[32];
__device__ float  g_ae2[8];
__device__ float  g_w2s[128];   // W2 @ as2 fold
__device__ float  g_w2d[128];   // W2 @ ad2 fold
__device__ float  g_gsum[NG * 32];
__device__ float  g_gcnt[NG];
// prepped bf16 split weights
#define B1C 168   // 128 (W1) + 4 (W1*as1) + 4 (W1*ad1) + 32 pad; 168 bf16 = 336B rows (bank-safe)
__device__ __align__(16) __nv_bfloat16 g_B1hi[128 * B1C];
__device__ __align__(16) __nv_bfloat16 g_B1lo[128 * B1C];
#define B2C 40    // 32 (W2) + 8 pad
__device__ __align__(16) __nv_bfloat16 g_B2hi[128 * B2C];
__device__ __align__(16) __nv_bfloat16 g_B2lo[128 * B2C];

__device__ __forceinline__ float leaky(float a) { return a > 0.f ? a : 0.2f * a; }
__device__ __forceinline__ float elu(float a)   { return a > 0.f ? a : expm1f(a); }

__device__ __forceinline__ void bsplit(float v, __nv_bfloat16& hi, __nv_bfloat16& lo) {
    hi = __float2bfloat16(v);
    lo = __float2bfloat16(v - __bfloat162float(hi));
}

// ---------------- zero accumulators ----------------
__global__ void k_zero() {
    int i = blockIdx.x * blockDim.x + threadIdx.x;
    if (i < NN) { g_deg[i] = 0; g_cursor[i] = 0; }
    if (i < NG * 32) g_gsum[i] = 0.f;
    if (i < NG) g_gcnt[i] = 0.f;
}

// ---------------- degree count, 4 edges/thread ----------------
__global__ void k_degree(const int* __restrict__ ei) {
    int i = blockIdx.x * blockDim.x + threadIdx.x;
    if (i >= NE / 4) return;
    int4 d4 = *(const int4*)(ei + NE + i * 4);
    atomicAdd(&g_deg[d4.x], 1);
    atomicAdd(&g_deg[d4.y], 1);
    atomicAdd(&g_deg[d4.z], 1);
    atomicAdd(&g_deg[d4.w], 1);
}

// ---------------- fast single-block scan ----------------
__global__ void k_scan() {
    __shared__ int warpsum[32];
    const int CH = (NN + 1023) / 1024;
    int t = threadIdx.x, lane = t & 31, wid = t >> 5;
    int beg = t * CH, end = beg + CH; if (end > NN) end = NN; if (beg > NN) beg = NN;
    int s = 0;
    for (int i = beg; i < end; i++) s += g_deg[i];
    int v = s;
    #pragma unroll
    for (int o = 1; o < 32; o <<= 1) {
        int u = __shfl_up_sync(0xffffffffu, v, o);
        if (lane >= o) v += u;
    }
    if (lane == 31) warpsum[wid] = v;
    __syncthreads();
    if (wid == 0) {
        int w = warpsum[lane];
        #pragma unroll
        for (int o = 1; o < 32; o <<= 1) {
            int u = __shfl_up_sync(0xffffffffu, w, o);
            if (lane >= o) w += u;
        }
        warpsum[lane] = w;
    }
    __syncthreads();
    int run = (wid > 0 ? warpsum[wid - 1] : 0) + (v - s);
    for (int i = beg; i < end; i++) { run += g_deg[i]; g_off[i + 1] = run; }
    if (t == 0) g_off[0] = 0;
}

// ---------------- CSR fill, 4 edges/thread ----------------
__global__ void k_fill(const int* __restrict__ ei) {
    int i = blockIdx.x * blockDim.x + threadIdx.x;
    if (i >= NE / 4) return;
    int4 d4 = *(const int4*)(ei + NE + i * 4);
    int e = i * 4;
    g_csr[g_off[d4.x] + atomicAdd(&g_cursor[d4.x], 1)] = e;
    g_csr[g_off[d4.y] + atomicAdd(&g_cursor[d4.y], 1)] = e + 1;
    g_csr[g_off[d4.z] + atomicAdd(&g_cursor[d4.z], 1)] = e + 2;
    g_csr[g_off[d4.w] + atomicAdd(&g_cursor[d4.w], 1)] = e + 3;
}

// ---------------- prep: folds + bf16 split weight buffers ----------------
__global__ void k_prep(const float* __restrict__ W1, const float* __restrict__ as1,
                       const float* __restrict__ ad1,
                       const float* __restrict__ We1, const float* __restrict__ ae1,
                       const float* __restrict__ W2, const float* __restrict__ as2,
                       const float* __restrict__ ad2,
                       const float* __restrict__ We2, const float* __restrict__ ae2) {
    __shared__ float sWas[128 * 4], sWad[128 * 4];
    int t = threadIdx.x;
    // W1 * att_src1 / att_dst1 (per head): [128][4]
    for (int i = t; i < 512; i += 256) {
        int k = i >> 2, h = i & 3;
        float ss = 0.f, sd = 0.f;
        for (int c = 0; c < 32; c++) {
            float w = W1[k * 128 + h * 32 + c];
            ss += w * as1[h * 32 + c];
            sd += w * ad1[h * 32 + c];
        }
        sWas[i] = ss; sWad[i] = sd;
    }
    // W2 folds
    for (int i = t; i < 128; i += 256) {
        float ss = 0.f, sd = 0.f;
        for (int c = 0; c < 32; c++) {
            float w = W2[i * 32 + c];
            ss += w * as2[c]; sd += w * ad2[c];
        }
        g_w2s[i] = ss; g_w2d[i] = sd;
    }
    // edge-attr folds
    if (t < 32) {
        int d = t >> 2, h = t & 3;
        float s = 0.f;
        for (int c = 0; c < 32; c++) s += We1[d * 128 + h * 32 + c] * ae1[h * 32 + c];
        g_ae1[d * 4 + h] = s;
    }
    if (t < 8) {
        float s = 0.f;
        for (int c = 0; c < 32; c++) s += We2[t * 32 + c] * ae2[c];
        g_ae2[t] = s;
    }
    __syncthreads();
    // B1 = [W1 | W1as | W1ad | 0] as bf16 hi/lo, [128][168]
    for (int i = t; i < 128 * B1C; i += 256) {
        int k = i / B1C, c = i % B1C;
        float v = 0.f;
        if (c < 128) v = W1[k * 128 + c];
        else if (c < 132) v = sWas[k * 4 + (c - 128)];
        else if (c < 136) v = sWad[k * 4 + (c - 132)];
        __nv_bfloat16 hi, lo; bsplit(v, hi, lo);
        g_B1hi[i] = hi; g_B1lo[i] = lo;
    }
    // B2 = [W2 | 0] bf16 hi/lo, [128][40]
    for (int i = t; i < 128 * B2C; i += 256) {
        int k = i / B2C, c = i % B2C;
        float v = (c < 32) ? W2[k * 32 + c] : 0.f;
        __nv_bfloat16 hi, lo; bsplit(v, hi, lo);
        g_B2hi[i] = hi; g_B2lo[i] = lo;
    }
}

// ---------------- GEMM1: h1 = x @ [W1|Was|Wad] via wmma bf16-split ----------------
__global__ __launch_bounds__(256) void k_gemm1(const float* __restrict__ x) {
    __shared__ __nv_bfloat16 sAhi[128 * 24], sAlo[128 * 24];
    __shared__ __nv_bfloat16 sBhi[16 * B1C], sBlo[16 * B1C];
    __shared__ float sStage[8 * 16 * 20];
    int t = threadIdx.x, wid = t >> 5, lane = t & 31;
    int n0 = blockIdx.x * 128;

    wmma::fragment<wmma::accumulator, 16, 16, 16, float> fc[9];
    #pragma unroll
    for (int j = 0; j < 9; j++) wmma::fill_fragment(fc[j], 0.f);

    for (int kc = 0; kc < 128; kc += 16) {
        // A tile: 128 rows x 16 cols, split bf16
        {
            int row = t >> 1, half = t & 1;
            float4 v0 = make_float4(0.f,0.f,0.f,0.f), v1 = v0;
            if (n0 + row < NN) {
                const float* src = x + (size_t)(n0 + row) * 128 + kc + half * 8;
                v0 = *(const float4*)src;
                v1 = *(const float4*)(src + 4);
            }
            __nv_bfloat16* hp = sAhi + row * 24 + half * 8;
            __nv_bfloat16* lp = sAlo + row * 24 + half * 8;
            float vv[8] = {v0.x, v0.y, v0.z, v0.w, v1.x, v1.y, v1.z, v1.w};
            #pragma unroll
            for (int q = 0; q < 8; q++) bsplit(vv[q], hp[q], lp[q]);
        }
        // B tile: 16 rows x 168 cols (float4 = 8 bf16; 21 per row)
        {
            const float4* gh = (const float4*)g_B1hi;
            const float4* gl = (const float4*)g_B1lo;
            float4* shh = (float4*)sBhi;
            float4* sll = (float4*)sBlo;
            for (int i = t; i < 16 * 21; i += 256) {
                int r = i / 21, c = i % 21;
                shh[r * 21 + c] = gh[(kc + r) * 21 + c];
                sll[r * 21 + c] = gl[(kc + r) * 21 + c];
            }
        }
        __syncthreads();
        wmma::fragment<wmma::matrix_a, 16, 16, 16, __nv_bfloat16, wmma::row_major> fahi, falo;
        wmma::load_matrix_sync(fahi, sAhi + wid * 16 * 24, 24);
        wmma::load_matrix_sync(falo, sAlo + wid * 16 * 24, 24);
        #pragma unroll
        for (int j = 0; j < 9; j++) {
            wmma::fragment<wmma::matrix_b, 16, 16, 16, __nv_bfloat16, wmma::row_major> fbhi, fblo;
            wmma::load_matrix_sync(fbhi, sBhi + j * 16, B1C);
            wmma::load_matrix_sync(fblo, sBlo + j * 16, B1C);
            wmma::mma_sync(fc[j], fahi, fbhi, fc[j]);
            wmma::mma_sync(fc[j], fahi, fblo, fc[j]);
            wmma::mma_sync(fc[j], falo, fbhi, fc[j]);
        }
        __syncthreads();
    }
    int rbase = n0 + wid * 16;
    if (rbase < NN) {   // 16 | 50000, so tiles are all-in or all-out
        #pragma unroll
        for (int j = 0; j < 8; j++)
            wmma::store_matrix_sync(&g_h1[(size_t)rbase * 128 + j * 16], fc[j], 128, wmma::mem_row_major);
        // tile 8 holds [als1 (4) | ald1 (4) | pad]
        wmma::store_matrix_sync(sStage + wid * 320, fc[8], 20, wmma::mem_row_major);
        __syncwarp();
        if (lane < 16) {
            const float* st = sStage + wid * 320 + lane * 20;
            int n = rbase + lane;
            #pragma unroll
            for (int h = 0; h < 4; h++) {
                g_als1[n * 4 + h] = st[h];
                g_ald1[n * 4 + h] = st[4 + h];
            }
        }
    }
}

// ---------------- per-edge alpha + edge term for conv1 ----------------
__global__ void k_alpha1(const int* __restrict__ ei, const float* __restrict__ ea) {
    __shared__ float sae[32];
    if (threadIdx.x < 32) sae[threadIdx.x] = g_ae1[threadIdx.x];
    __syncthreads();
    int e = blockIdx.x * blockDim.x + threadIdx.x;
    if (e >= NE) return;
    int s = ei[e], d = ei[NE + e];
    float4 a0 = *(const float4*)(ea + (size_t)e * 8);
    float4 a1 = *(const float4*)(ea + (size_t)e * 8 + 4);
    float av[8] = {a0.x, a0.y, a0.z, a0.w, a1.x, a1.y, a1.z, a1.w};
    float t0 = 0.f, t1 = 0.f, t2 = 0.f, t3 = 0.f;
    #pragma unroll
    for (int j = 0; j < 8; j++) {
        t0 += av[j] * sae[j * 4 + 0]; t1 += av[j] * sae[j * 4 + 1];
        t2 += av[j] * sae[j * 4 + 2]; t3 += av[j] * sae[j * 4 + 3];
    }
    g_t1[e] = make_float4(t0, t1, t2, t3);
    float4 al;
    al.x = leaky(g_als1[s * 4 + 0] + g_ald1[d * 4 + 0] + t0);
    al.y = leaky(g_als1[s * 4 + 1] + g_ald1[d * 4 + 1] + t1);
    al.z = leaky(g_als1[s * 4 + 2] + g_ald1[d * 4 + 2] + t2);
    al.w = leaky(g_als1[s * 4 + 3] + g_ald1[d * 4 + 3] + t3);
    g_alpha1[e] = al;
}

// ---------------- conv1 aggregation (no-max softmax) + fused als2/ald2 ----------------
__global__ void k_agg1(const int* __restrict__ ei, const float* __restrict__ b1) {
    int n = (blockIdx.x * blockDim.x + threadIdx.x) >> 5;
    int lane = threadIdx.x & 31;
    if (n >= NN) return;
    int beg = g_off[n], end = g_off[n + 1];
    float den[4] = {0.f,0.f,0.f,0.f}, acc[4] = {0.f,0.f,0.f,0.f}, ts[4] = {0.f,0.f,0.f,0.f};
    for (int j = beg; j < end; j++) {
        int eid = g_csr[j];
        int s = ei[eid];
        float4 a4 = g_alpha1[eid];
        float4 t4 = g_t1[eid];
        ts[0] += t4.x; ts[1] += t4.y; ts[2] += t4.z; ts[3] += t4.w;
        const float* hrow = g_h1 + (size_t)s * 128 + lane;
        float w0 = __expf(a4.x), w1 = __expf(a4.y), w2 = __expf(a4.z), w3 = __expf(a4.w);
        den[0] += w0; acc[0] += w0 * hrow[0];
        den[1] += w1; acc[1] += w1 * hrow[32];
        den[2] += w2; acc[2] += w2 * hrow[64];
        den[3] += w3; acc[3] += w3 * hrow[96];
    }
    int cnt = end - beg;
    float inv = cnt > 0 ? 1.f / (float)cnt : 0.f;
    const float* hn = g_h1 + (size_t)n * 128 + lane;
    float o[4];
    #pragma unroll
    for (int r = 0; r < 4; r++) {
        float aa = leaky(g_als1[n * 4 + r] + g_ald1[n * 4 + r] + ts[r] * inv);
        float w = __expf(aa);
        den[r] += w;
        acc[r] += w * hn[r * 32];
        o[r] = elu(acc[r] / (den[r] + 1e-16f) + b1[r * 32 + lane]);
        g_out1[(size_t)n * 128 + r * 32 + lane] = o[r];
    }
    // fused als2/ald2 = out1[n] . w2s / w2d
    float ps = 0.f, pd = 0.f;
    #pragma unroll
    for (int r = 0; r < 4; r++) {
        ps += o[r] * g_w2s[r * 32 + lane];
        pd += o[r] * g_w2d[r * 32 + lane];
    }
    #pragma unroll
    for (int off = 16; off; off >>= 1) {
        ps += __shfl_xor_sync(0xffffffffu, ps, off);
        pd += __shfl_xor_sync(0xffffffffu, pd, off);
    }
    if (lane == 0) { g_als2[n] = ps; g_ald2[n] = pd; }
}

// ---------------- GEMM2: h2 = out1 @ W2 via wmma bf16-split ----------------
__global__ __launch_bounds__(256) void k_gemm2() {
    __shared__ __nv_bfloat16 sAhi[128 * 24], sAlo[128 * 24];
    __shared__ __nv_bfloat16 sBhi[128 * B2C], sBlo[128 * B2C];
    int t = threadIdx.x, wid = t >> 5;
    int n0 = blockIdx.x * 128;
    // load whole B once
    {
        const float4* gh = (const float4*)g_B2hi;
        const float4* gl = (const float4*)g_B2lo;
        float4* shh = (float4*)sBhi;
        float4* sll = (float4*)sBlo;
        for (int i = t; i < 128 * B2C / 8; i += 256) { shh[i] = gh[i]; sll[i] = gl[i]; }
    }
    wmma::fragment<wmma::accumulator, 16, 16, 16, float> fc[2];
    wmma::fill_fragment(fc[0], 0.f);
    wmma::fill_fragment(fc[1], 0.f);

    for (int kc = 0; kc < 128; kc += 16) {
        {
            int row = t >> 1, half = t & 1;
            float4 v0 = make_float4(0.f,0.f,0.f,0.f), v1 = v0;
            if (n0 + row < NN) {
                const float* src = g_out1 + (size_t)(n0 + row) * 128 + kc + half * 8;
                v0 = *(const float4*)src;
                v1 = *(const float4*)(src + 4);
            }
            __nv_bfloat16* hp = sAhi + row * 24 + half * 8;
            __nv_bfloat16* lp = sAlo + row * 24 + half * 8;
            float vv[8] = {v0.x, v0.y, v0.z, v0.w, v1.x, v1.y, v1.z, v1.w};
            #pragma unroll
            for (int q = 0; q < 8; q++) bsplit(vv[q], hp[q], lp[q]);
        }
        __syncthreads();
        wmma::fragment<wmma::matrix_a, 16, 16, 16, __nv_bfloat16, wmma::row_major> fahi, falo;
        wmma::load_matrix_sync(fahi, sAhi + wid * 16 * 24, 24);
        wmma::load_matrix_sync(falo, sAlo + wid * 16 * 24, 24);
        #pragma unroll
        for (int j = 0; j < 2; j++) {
            wmma::fragment<wmma::matrix_b, 16, 16, 16, __nv_bfloat16, wmma::row_major> fbhi, fblo;
            wmma::load_matrix_sync(fbhi, sBhi + kc * B2C + j * 16, B2C);
            wmma::load_matrix_sync(fblo, sBlo + kc * B2C + j * 16, B2C);
            wmma::mma_sync(fc[j], fahi, fbhi, fc[j]);
            wmma::mma_sync(fc[j], fahi, fblo, fc[j]);
            wmma::mma_sync(fc[j], falo, fbhi, fc[j]);
        }
        __syncthreads();
    }
    int rbase = n0 + wid * 16;
    if (rbase < NN) {
        wmma::store_matrix_sync(&g_h2[(size_t)rbase * 32], fc[0], 32, wmma::mem_row_major);
        wmma::store_matrix_sync(&g_h2[(size_t)rbase * 32 + 16], fc[1], 32, wmma::mem_row_major);
    }
}

// ---------------- per-edge alpha + edge term for conv2 ----------------
__global__ void k_alpha2(const int* __restrict__ ei, const float* __restrict__ ea) {
    __shared__ float sae[8];
    if (threadIdx.x < 8) sae[threadIdx.x] = g_ae2[threadIdx.x];
    __syncthreads();
    int e = blockIdx.x * blockDim.x + threadIdx.x;
    if (e >= NE) return;
    int s = ei[e], d = ei[NE + e];
    float4 a0 = *(const float4*)(ea + (size_t)e * 8);
    float4 a1 = *(const float4*)(ea + (size_t)e * 8 + 4);
    float tt = a0.x * sae[0] + a0.y * sae[1] + a0.z * sae[2] + a0.w * sae[3]
             + a1.x * sae[4] + a1.y * sae[5] + a1.z * sae[6] + a1.w * sae[7];
    g_t2[e] = tt;
    g_alpha2[e] = leaky(g_als2[s] + g_ald2[d] + tt);
}

// ---------------- conv2 aggregation (no-max) + fused mean-pool ----------------
__global__ void k_agg2(const int* __restrict__ ei, const float* __restrict__ b2,
                       const int* __restrict__ batch) {
    int n = (blockIdx.x * blockDim.x + threadIdx.x) >> 5;
    int lane = threadIdx.x & 31;
    if (n >= NN) return;
    int beg = g_off[n], end = g_off[n + 1];
    float den = 0.f, acc = 0.f, tsum = 0.f;
    for (int j = beg; j < end; j++) {
        int eid = g_csr[j];
        int s = ei[eid];
        tsum += g_t2[eid];
        float w = __expf(g_alpha2[eid]);
        den += w;
        acc += w * g_h2[(size_t)s * 32 + lane];
    }
    int cnt = end - beg;
    float inv = cnt > 0 ? 1.f / (float)cnt : 0.f;
    float w = __expf(leaky(g_als2[n] + g_ald2[n] + tsum * inv));
    den += w;
    acc += w * g_h2[(size_t)n * 32 + lane];

    float val = elu(acc / (den + 1e-16f) + b2[lane]);
    int b = batch[n];
    atomicAdd(&g_gsum[b * 32 + lane], val);
    if (lane == 0) atomicAdd(&g_gcnt[b], 1.f);
}

// ---------------- final MLP head ----------------
__global__ void k_final(const float* __restrict__ W3, const float* __restrict__ b3,
                        const float* __restrict__ W4, const float* __restrict__ b4,
                        float* __restrict__ out) {
    int t = threadIdx.x;
    if (t >= NG) return;
    float c = fmaxf(g_gcnt[t], 1.f);
    float g[32];
    #pragma unroll
    for (int i = 0; i < 32; i++) g[i] = g_gsum[t * 32 + i] / c;
    float z[16];
    #pragma unroll
    for (int j = 0; j < 16; j++) {
        float s = b3[j];
        #pragma unroll
        for (int i = 0; i < 32; i++) s += g[i] * W3[i * 16 + j];
        z[j] = fmaxf(s, 0.f);
    }
    #pragma unroll
    for (int o = 0; o < 10; o++) {
        float s = b4[o];
        #pragma unroll
        for (int j = 0; j < 16; j++) s += z[j] * W4[j * 10 + o];
        out[t * 10 + o] = s;
    }
}

extern "C" void kernel_launch(void* const* d_in, const int* in_sizes, int n_in,
                              void* d_out, int out_size) {
    const float* x     = (const float*)d_in[0];
    const int*   ei    = (const int*)d_in[1];
    const float* ea    = (const float*)d_in[2];
    const int*   batch = (const int*)d_in[3];
    const float* W1    = (const float*)d_in[4];
    const float* as1   = (const float*)d_in[5];
    const float* ad1   = (const float*)d_in[6];
    const float* We1   = (const float*)d_in[7];
    const float* ae1   = (const float*)d_in[8];
    const float* b1    = (const float*)d_in[9];
    const float* W2    = (const float*)d_in[10];
    const float* as2   = (const float*)d_in[11];
    const float* ad2   = (const float*)d_in[12];
    const float* We2   = (const float*)d_in[13];
    const float* ae2   = (const float*)d_in[14];
    const float* b2    = (const float*)d_in[15];
    const float* W3    = (const float*)d_in[16];
    const float* b3    = (const float*)d_in[17];
    const float* W4    = (const float*)d_in[18];
    const float* b4    = (const float*)d_in[19];
    float* out = (float*)d_out;

    k_zero   <<<(NN + 255) / 256, 256>>>();
    k_degree <<<(NE / 4 + 255) / 256, 256>>>(ei);
    k_prep   <<<1, 256>>>(W1, as1, ad1, We1, ae1, W2, as2, ad2, We2, ae2);
    k_gemm1  <<<(NN + 127) / 128, 256>>>(x);         // launch idx 3 -> profiled
    k_scan   <<<1, 1024>>>();
    k_fill   <<<(NE / 4 + 255) / 256, 256>>>(ei);
    k_alpha1 <<<(NE + 255) / 256, 256>>>(ei, ea);
    k_agg1   <<<(NN + 7) / 8, 256>>>(ei, b1);
    k_gemm2  <<<(NN + 127) / 128, 256>>>();
    k_alpha2 <<<(NE + 255) / 256, 256>>>(ei, ea);
    k_agg2   <<<(NN + 7) / 8, 256>>>(ei, b2, batch);
    k_final  <<<1, 64>>>(W3, b3, W4, b4, out);
}